// round 4
// baseline (speedup 1.0000x reference)
#include <cuda_runtime.h>

#define N_TOTAL 65536
#define NNZ (16 * N_TOTAL)
#define STEPS 16
#define NBLK 256          // stepper blocks (256 x 256 threads = N_TOTAL)
#define TB 256

// ---------------------------------------------------------------------------
// Device-global scratch (allocation-free).
__device__ float2 g_U[2][N_TOTAL];        // interleaved (Ur, Ui) ping-pong
__device__ unsigned g_count[N_TOTAL];     // row histogram
__device__ unsigned g_rowptr[N_TOTAL + 1];
__device__ unsigned g_rofs[N_TOTAL];      // running fill offsets
__device__ int2     g_pairs[NNZ];         // {col, val*dz (bitcast)} CSR-sorted
__device__ unsigned g_bar_count;          // grid barrier counter

// ---------------------------------------------------------------------------
// K1: zero counts, reset barrier, load U0 as interleaved float2.
__global__ void init_kernel(const float* __restrict__ Ur0,
                            const float* __restrict__ Ui0) {
    int i = blockIdx.x * blockDim.x + threadIdx.x;
    if (i < N_TOTAL) {
        g_count[i] = 0;
        g_U[0][i] = make_float2(Ur0[i], Ui0[i]);
    }
    if (i == 0) g_bar_count = 0;
}

// K2: row histogram.
__global__ void hist_kernel(const int* __restrict__ row_idx) {
    int i = blockIdx.x * blockDim.x + threadIdx.x;
    if (i < NNZ) atomicAdd(&g_count[row_idx[i]], 1u);
}

// K3: exclusive scan of 65536 counts with a single 1024-thread block.
__global__ void scan_kernel() {
    __shared__ unsigned s_sums[1024];
    int t = threadIdx.x;
    int base = t * 64;
    unsigned sum = 0;
    #pragma unroll 4
    for (int i = 0; i < 64; i++) sum += g_count[base + i];
    s_sums[t] = sum;
    __syncthreads();
    // inclusive Hillis-Steele scan over the 1024 chunk sums
    for (int off = 1; off < 1024; off <<= 1) {
        unsigned v = (t >= off) ? s_sums[t - off] : 0u;
        __syncthreads();
        s_sums[t] += v;
        __syncthreads();
    }
    unsigned run = (t == 0) ? 0u : s_sums[t - 1];
    for (int i = 0; i < 64; i++) {
        g_rowptr[base + i] = run;
        g_rofs[base + i]   = run;
        run += g_count[base + i];
    }
    if (t == 1023) g_rowptr[N_TOTAL] = run;   // == NNZ
}

// K4: fill CSR pairs, prescaling values by dz.
__global__ void fill_kernel(const float* __restrict__ A_vals,
                            const int* __restrict__ row_idx,
                            const int* __restrict__ col_idx,
                            float dz) {
    int i = blockIdx.x * blockDim.x + threadIdx.x;
    if (i >= NNZ) return;
    int r = row_idx[i];
    unsigned pos = atomicAdd(&g_rofs[r], 1u);
    g_pairs[pos] = make_int2(col_idx[i], __float_as_int(A_vals[i] * dz));
}

// ---------------------------------------------------------------------------
// Software grid barrier (round s: wait until (s+1)*NBLK arrivals).
__device__ __forceinline__ void grid_bar(int round) {
    __syncthreads();
    __threadfence();                       // release my writes
    if (threadIdx.x == 0) {
        atomicAdd(&g_bar_count, 1u);
        unsigned target = (unsigned)(round + 1) * NBLK;
        volatile unsigned* p = &g_bar_count;
        while (*p < target) { }
        __threadfence();                   // acquire others' writes
    }
    __syncthreads();
}

// K5: persistent stepper — all 16 Euler steps + planar output write.
// Thread r owns row r; rowptr cached in registers across steps; no atomics.
__global__ __launch_bounds__(TB) void step_kernel(float* __restrict__ out) {
    int r = blockIdx.x * TB + threadIdx.x;
    const unsigned start = g_rowptr[r];
    const unsigned end   = g_rowptr[r + 1];
    int src = 0;
    #pragma unroll 1
    for (int s = 0; s < STEPS; s++) {
        const float2* __restrict__ U = g_U[src];
        float sr = 0.f, si = 0.f;
        for (unsigned j = start; j < end; j++) {
            int2 p = g_pairs[j];
            float v = __int_as_float(p.y);
            float2 u = __ldg(&U[p.x]);
            sr = fmaf(v, u.y, sr);        // dz * (A @ Ui)[r]
            si = fmaf(v, u.x, si);        // dz * (A @ Ur)[r]
        }
        float2 mine = U[r];
        g_U[src ^ 1][r] = make_float2(mine.x - sr, mine.y + si);
        src ^= 1;
        if (s != STEPS - 1) grid_bar(s);
    }
    float2 fin = g_U[src][r];
    out[r]           = fin.x;
    out[N_TOTAL + r] = fin.y;
}

// ---------------------------------------------------------------------------
extern "C" void kernel_launch(void* const* d_in, const int* in_sizes, int n_in,
                              void* d_out, int out_size) {
    const float* A_vals  = (const float*)d_in[0];
    const int*   row_idx = (const int*)d_in[1];
    const int*   col_idx = (const int*)d_in[2];
    const float* Ur0     = (const float*)d_in[3];
    const float* Ui0     = (const float*)d_in[4];
    const float dz = 1.0f / (float)STEPS;

    init_kernel<<<(N_TOTAL + TB - 1) / TB, TB>>>(Ur0, Ui0);
    hist_kernel<<<(NNZ + TB - 1) / TB, TB>>>(row_idx);
    scan_kernel<<<1, 1024>>>();
    fill_kernel<<<(NNZ + TB - 1) / TB, TB>>>(A_vals, row_idx, col_idx, dz);
    step_kernel<<<NBLK, TB>>>((float*)d_out);
}

// round 5
// speedup vs baseline: 2.4313x; 2.4313x over previous
#include <cuda_runtime.h>

#define N_TOTAL 65536
#define NNZ (16 * N_TOTAL)
#define STEPS 16
#define MAXW 64
#define TB 256

// ---------------------------------------------------------------------------
// Device-global scratch (allocation-free).
__device__ float2   g_U[2][N_TOTAL];            // interleaved (Ur,Ui) ping-pong
__device__ unsigned g_cnt[N_TOTAL];             // per-row nnz count / fill cursor
__device__ int2     g_pairs[MAXW * N_TOTAL];    // ELL slot-major: [slot*N + row]

// ---------------------------------------------------------------------------
// K1: zero counts, pack U0 into interleaved float2.
__global__ void init_kernel(const float* __restrict__ Ur0,
                            const float* __restrict__ Ui0) {
    int i = blockIdx.x * blockDim.x + threadIdx.x;
    if (i < N_TOTAL) {
        g_cnt[i] = 0;
        g_U[0][i] = make_float2(Ur0[i], Ui0[i]);
    }
}

// K2: single-pass ELL fill. pos within row comes from the atomic itself.
// Vectorized x4 for ILP (NNZ % 4 == 0; inputs are cudaMalloc'd -> 16B aligned).
__global__ __launch_bounds__(TB)
void fill_kernel(const float4* __restrict__ A4,
                 const int4* __restrict__ R4,
                 const int4* __restrict__ C4, float dz) {
    int i = blockIdx.x * blockDim.x + threadIdx.x;
    if (i >= NNZ / 4) return;
    float4 a = A4[i];
    int4   r = R4[i];
    int4   c = C4[i];
    unsigned p0 = atomicAdd(&g_cnt[r.x], 1u);
    unsigned p1 = atomicAdd(&g_cnt[r.y], 1u);
    unsigned p2 = atomicAdd(&g_cnt[r.z], 1u);
    unsigned p3 = atomicAdd(&g_cnt[r.w], 1u);
    g_pairs[p0 * N_TOTAL + r.x] = make_int2(c.x, __float_as_int(a.x * dz));
    g_pairs[p1 * N_TOTAL + r.y] = make_int2(c.y, __float_as_int(a.y * dz));
    g_pairs[p2 * N_TOTAL + r.z] = make_int2(c.z, __float_as_int(a.z * dz));
    g_pairs[p3 * N_TOTAL + r.w] = make_int2(c.w, __float_as_int(a.w * dz));
}

// ---------------------------------------------------------------------------
// K3: one Euler step. Thread r owns row r. Slot-major pair loads are fully
// coalesced; float2 gathers from the L2-resident src state; no atomics; the
// ping-pong write doubles as the "copy". FINAL also writes planar output.
template <bool FINAL>
__global__ __launch_bounds__(TB)
void step_kernel(int src, float* __restrict__ out) {
    int r = blockIdx.x * TB + threadIdx.x;
    const float2* __restrict__ U = g_U[src];
    const unsigned cnt = g_cnt[r];
    float sr = 0.f, si = 0.f;
    unsigned j = 0;
    for (; j + 4 <= cnt; j += 4) {
        int2 p0 = g_pairs[(j + 0) * N_TOTAL + r];
        int2 p1 = g_pairs[(j + 1) * N_TOTAL + r];
        int2 p2 = g_pairs[(j + 2) * N_TOTAL + r];
        int2 p3 = g_pairs[(j + 3) * N_TOTAL + r];
        float2 u0 = __ldg(&U[p0.x]);
        float2 u1 = __ldg(&U[p1.x]);
        float2 u2 = __ldg(&U[p2.x]);
        float2 u3 = __ldg(&U[p3.x]);
        float v0 = __int_as_float(p0.y), v1 = __int_as_float(p1.y);
        float v2 = __int_as_float(p2.y), v3 = __int_as_float(p3.y);
        sr = fmaf(v0, u0.y, sr);  si = fmaf(v0, u0.x, si);
        sr = fmaf(v1, u1.y, sr);  si = fmaf(v1, u1.x, si);
        sr = fmaf(v2, u2.y, sr);  si = fmaf(v2, u2.x, si);
        sr = fmaf(v3, u3.y, sr);  si = fmaf(v3, u3.x, si);
    }
    for (; j < cnt; j++) {
        int2 p = g_pairs[j * N_TOTAL + r];
        float2 u = __ldg(&U[p.x]);
        float v = __int_as_float(p.y);
        sr = fmaf(v, u.y, sr);
        si = fmaf(v, u.x, si);
    }
    float2 mine = U[r];
    float2 nxt = make_float2(mine.x - sr, mine.y + si);
    g_U[src ^ 1][r] = nxt;
    if (FINAL) {
        out[r]           = nxt.x;
        out[N_TOTAL + r] = nxt.y;
    }
}

// ---------------------------------------------------------------------------
extern "C" void kernel_launch(void* const* d_in, const int* in_sizes, int n_in,
                              void* d_out, int out_size) {
    const float* A_vals  = (const float*)d_in[0];
    const int*   row_idx = (const int*)d_in[1];
    const int*   col_idx = (const int*)d_in[2];
    const float* Ur0     = (const float*)d_in[3];
    const float* Ui0     = (const float*)d_in[4];
    const float dz = 1.0f / (float)STEPS;

    init_kernel<<<(N_TOTAL + TB - 1) / TB, TB>>>(Ur0, Ui0);
    fill_kernel<<<(NNZ / 4 + TB - 1) / TB, TB>>>(
        (const float4*)A_vals, (const int4*)row_idx, (const int4*)col_idx, dz);

    int src = 0;
    for (int s = 0; s < STEPS - 1; s++) {
        step_kernel<false><<<N_TOTAL / TB, TB>>>(src, nullptr);
        src ^= 1;
    }
    step_kernel<true><<<N_TOTAL / TB, TB>>>(src, (float*)d_out);
}

// round 6
// speedup vs baseline: 2.9966x; 1.2325x over previous
#include <cuda_runtime.h>

#define N_TOTAL 65536
#define NNZ (16 * N_TOTAL)
#define STEPS 16
#define MAXW 64
#define TB 256
#define PARTS 4
#define ROWS_PER_BLK (TB / PARTS)   // 64 rows per block

// ---------------------------------------------------------------------------
// Device-global scratch (allocation-free).
__device__ float2   g_U[2][N_TOTAL];            // interleaved (Ur,Ui) ping-pong
__device__ unsigned g_cnt[N_TOTAL];             // per-row nnz count / fill cursor
__device__ int2     g_pairs[MAXW * N_TOTAL];    // ELL slot-major: [slot*N + row]

// ---------------------------------------------------------------------------
// K1: zero counts, pack U0 into interleaved float2.
__global__ void init_kernel(const float* __restrict__ Ur0,
                            const float* __restrict__ Ui0) {
    int i = blockIdx.x * blockDim.x + threadIdx.x;
    if (i < N_TOTAL) {
        g_cnt[i] = 0;
        g_U[0][i] = make_float2(Ur0[i], Ui0[i]);
    }
}

// K2: single-pass ELL fill; slot position comes straight from the atomic.
__global__ __launch_bounds__(TB)
void fill_kernel(const float4* __restrict__ A4,
                 const int4* __restrict__ R4,
                 const int4* __restrict__ C4, float dz) {
    int i = blockIdx.x * blockDim.x + threadIdx.x;
    if (i >= NNZ / 4) return;
    float4 a = A4[i];
    int4   r = R4[i];
    int4   c = C4[i];
    unsigned p0 = atomicAdd(&g_cnt[r.x], 1u);
    unsigned p1 = atomicAdd(&g_cnt[r.y], 1u);
    unsigned p2 = atomicAdd(&g_cnt[r.z], 1u);
    unsigned p3 = atomicAdd(&g_cnt[r.w], 1u);
    g_pairs[p0 * N_TOTAL + r.x] = make_int2(c.x, __float_as_int(a.x * dz));
    g_pairs[p1 * N_TOTAL + r.y] = make_int2(c.y, __float_as_int(a.y * dz));
    g_pairs[p2 * N_TOTAL + r.z] = make_int2(c.z, __float_as_int(a.z * dz));
    g_pairs[p3 * N_TOTAL + r.w] = make_int2(c.w, __float_as_int(a.w * dz));
}

// ---------------------------------------------------------------------------
// K3: one Euler step, 4 lanes per row. part = tid>>6 so each warp covers 32
// consecutive rows at one part -> slot-major pair loads stay fully coalesced.
// Partials reduced via smem; part 0 writes the ping-pong (and final output).
template <bool FINAL>
__global__ __launch_bounds__(TB)
void step_kernel(int src, float* __restrict__ out) {
    __shared__ float s_r[PARTS][ROWS_PER_BLK];
    __shared__ float s_i[PARTS][ROWS_PER_BLK];

    const int part = threadIdx.x >> 6;          // 0..3
    const int lr   = threadIdx.x & (ROWS_PER_BLK - 1);
    const int r    = blockIdx.x * ROWS_PER_BLK + lr;

    const float2* __restrict__ U = g_U[src];
    const unsigned cnt = g_cnt[r];

    float sr = 0.f, si = 0.f;
    #pragma unroll 4
    for (unsigned j = part; j < cnt; j += PARTS) {
        int2 p = g_pairs[j * N_TOTAL + r];
        float2 u = __ldg(&U[p.x]);
        float v = __int_as_float(p.y);
        sr = fmaf(v, u.y, sr);                  // dz*(A@Ui)[r]
        si = fmaf(v, u.x, si);                  // dz*(A@Ur)[r]
    }
    s_r[part][lr] = sr;
    s_i[part][lr] = si;
    __syncthreads();

    if (part == 0) {
        float tr = s_r[0][lr] + s_r[1][lr] + s_r[2][lr] + s_r[3][lr];
        float ti = s_i[0][lr] + s_i[1][lr] + s_i[2][lr] + s_i[3][lr];
        float2 mine = U[r];
        float2 nxt = make_float2(mine.x - tr, mine.y + ti);
        g_U[src ^ 1][r] = nxt;
        if (FINAL) {
            out[r]           = nxt.x;
            out[N_TOTAL + r] = nxt.y;
        }
    }
}

// ---------------------------------------------------------------------------
extern "C" void kernel_launch(void* const* d_in, const int* in_sizes, int n_in,
                              void* d_out, int out_size) {
    const float* A_vals  = (const float*)d_in[0];
    const int*   row_idx = (const int*)d_in[1];
    const int*   col_idx = (const int*)d_in[2];
    const float* Ur0     = (const float*)d_in[3];
    const float* Ui0     = (const float*)d_in[4];
    const float dz = 1.0f / (float)STEPS;

    init_kernel<<<(N_TOTAL + TB - 1) / TB, TB>>>(Ur0, Ui0);
    fill_kernel<<<(NNZ / 4 + TB - 1) / TB, TB>>>(
        (const float4*)A_vals, (const int4*)row_idx, (const int4*)col_idx, dz);

    const int grid = N_TOTAL / ROWS_PER_BLK;    // 1024 blocks
    int src = 0;
    for (int s = 0; s < STEPS - 1; s++) {
        step_kernel<false><<<grid, TB>>>(src, nullptr);
        src ^= 1;
    }
    step_kernel<true><<<grid, TB>>>(src, (float*)d_out);
}